// round 13
// baseline (speedup 1.0000x reference)
#include <cuda_runtime.h>
#include <cuda_bf16.h>

// WeightAndSum: out[s, :] = sum_{r in segment s} feats[r,:] * sigmoid(dot(feats[r,:], w) + b)
// N = 2,000,000 rows, D = 128, B = 65536 segments, segment_ids sorted ascending.
//
// Two-kernel plan, zero atomics, zero memset:
//  1) offs_kernel (vectorized int4, shuffle for prev): g_offs[b] = first row
//     of segment b, g_offs[B] = N.
//  2) was_kernel (R6 loop shape — proven best): warp per segment, exclusive
//     ownership, branchless double-buffered 4-row pipeline, one float4 store
//     per lane per segment (empties store zeros). NEW: register-free
//     prefetch.global.L2 of the group 3 ahead (clamped to the global feats
//     range — rows past the segment end belong to the adjacent warp, so the
//     prefetch is still useful). Demand loads then hit L2 instead of DRAM,
//     cutting exposed latency without any extra registers or branches.
//     __fdividef sigmoid; PDL launch; THREADS=128.

#define D_DIM 128
#define THREADS 128
#define WARPS (THREADS / 32)
#define MAX_B 65536
#define PF_ROWS 12   // prefetch distance in rows (3 groups ahead)

#define SIGMOID(t) __fdividef(1.0f, 1.0f + __expf(-(t)))

__device__ int g_offs[MAX_B + 1];

__device__ __forceinline__ void pf_l2(const void* p) {
    asm volatile("prefetch.global.L2 [%0];" :: "l"(p));
}

__global__ __launch_bounds__(256) void offs_kernel(
    const int* __restrict__ seg, int N, int B)
{
    const int i    = blockIdx.x * blockDim.x + threadIdx.x;
    const int base = i * 4;
    const int lane = threadIdx.x & 31;

    int ids[4] = {0, 0, 0, 0};
    const bool active = (base < N);
    if (active) {
        if (base + 4 <= N) {
            const int4 v = *reinterpret_cast<const int4*>(seg + base);
            ids[0] = v.x; ids[1] = v.y; ids[2] = v.z; ids[3] = v.w;
        } else {
#pragma unroll
            for (int k = 0; k < 4; ++k)
                ids[k] = (base + k < N) ? __ldg(seg + base + k) : 0;
        }
    }

    // prev = seg[base-1]: lane l-1 holds it as ids[3]; warp-edge lanes load it
    const int up = __shfl_up_sync(0xffffffffu, ids[3], 1);
    int prev;
    if (lane == 0)
        prev = (base == 0) ? -1 : __ldg(seg + base - 1);
    else
        prev = up;

    if (!active) return;

    int p = prev;
#pragma unroll
    for (int k = 0; k < 4; ++k) {
        if (base + k >= N) break;
        const int s = ids[k];
        for (int bb = p + 1; bb <= s; ++bb) g_offs[bb] = base + k;
        p = s;
        if (base + k == N - 1)
            for (int bb = s + 1; bb <= B; ++bb) g_offs[bb] = N;
    }
}

__global__ __launch_bounds__(THREADS) void was_kernel(
    const float* __restrict__ feats,
    const float* __restrict__ w,
    const float* __restrict__ b,
    float*       __restrict__ out,
    int B, int N)
{
    const int wid  = threadIdx.x >> 5;
    const int lane = threadIdx.x & 31;
    const int s    = blockIdx.x * WARPS + wid;

    // setup that does NOT depend on g_offs — overlaps offs_kernel via PDL
    const float4 wv  = reinterpret_cast<const float4*>(w)[lane];
    const float bias = __ldg(b);

#if __CUDA_ARCH__ >= 900
    cudaGridDependencySynchronize();
#endif

    if (s >= B) return;

    const int start = __ldg(&g_offs[s]);
    const int end   = __ldg(&g_offs[s + 1]);

    float4 acc = make_float4(0.f, 0.f, 0.f, 0.f);

    int r = start;
    const int stop = start + ((end - start) & ~3);  // full 4-row groups
    const int pfMax = N - 4;                        // last legal prefetch group base

    if (r < stop) {
        // ---- prologue: load group 0, prefetch ahead ----
        const float4* base =
            reinterpret_cast<const float4*>(feats) + (size_t)r * (D_DIM / 4) + lane;
        float4 f0 = __ldcs(base);
        float4 f1 = __ldcs(base + (D_DIM / 4));
        float4 f2 = __ldcs(base + 2 * (D_DIM / 4));
        float4 f3 = __ldcs(base + 3 * (D_DIM / 4));
        {
            int rp = r + 4 + PF_ROWS > pfMax ? pfMax : r + 4 + PF_ROWS;
            if (rp < 0) rp = 0;
            const float4* pp =
                reinterpret_cast<const float4*>(feats) + (size_t)rp * (D_DIM / 4) + lane;
            pf_l2(pp);
            pf_l2(pp + (D_DIM / 4));
            pf_l2(pp + 2 * (D_DIM / 4));
            pf_l2(pp + 3 * (D_DIM / 4));
        }

        for (;;) {
            const int rn    = r + 4;
            const bool more = (rn < stop);

            // ---- prefetch next group (demand) before current chain ----
            float4 f0n, f1n, f2n, f3n;
            if (more) {
                const float4* bn =
                    reinterpret_cast<const float4*>(feats) + (size_t)rn * (D_DIM / 4) + lane;
                f0n = __ldcs(bn);
                f1n = __ldcs(bn + (D_DIM / 4));
                f2n = __ldcs(bn + 2 * (D_DIM / 4));
                f3n = __ldcs(bn + 3 * (D_DIM / 4));
            }

            // ---- register-free L2 prefetch, 3 groups ahead (clamped) ----
            {
                int rp = rn + PF_ROWS > pfMax ? pfMax : rn + PF_ROWS;
                if (rp < 0) rp = 0;
                const float4* pp =
                    reinterpret_cast<const float4*>(feats) + (size_t)rp * (D_DIM / 4) + lane;
                pf_l2(pp);
                pf_l2(pp + (D_DIM / 4));
                pf_l2(pp + 2 * (D_DIM / 4));
                pf_l2(pp + 3 * (D_DIM / 4));
            }

            // ---- 4 per-lane partial dots, 4 parallel butterflies ----
            float p0 = f0.x * wv.x + f0.y * wv.y + f0.z * wv.z + f0.w * wv.w;
            float p1 = f1.x * wv.x + f1.y * wv.y + f1.z * wv.z + f1.w * wv.w;
            float p2 = f2.x * wv.x + f2.y * wv.y + f2.z * wv.z + f2.w * wv.w;
            float p3 = f3.x * wv.x + f3.y * wv.y + f3.z * wv.z + f3.w * wv.w;

#pragma unroll
            for (int o = 16; o > 0; o >>= 1) {
                p0 += __shfl_xor_sync(0xffffffffu, p0, o);
                p1 += __shfl_xor_sync(0xffffffffu, p1, o);
                p2 += __shfl_xor_sync(0xffffffffu, p2, o);
                p3 += __shfl_xor_sync(0xffffffffu, p3, o);
            }

            const float g0 = SIGMOID(p0 + bias);
            const float g1 = SIGMOID(p1 + bias);
            const float g2 = SIGMOID(p2 + bias);
            const float g3 = SIGMOID(p3 + bias);

            // ---- branchless accumulate (single owner: no flush logic) ----
            acc.x += f0.x * g0 + f1.x * g1 + f2.x * g2 + f3.x * g3;
            acc.y += f0.y * g0 + f1.y * g1 + f2.y * g2 + f3.y * g3;
            acc.z += f0.z * g0 + f1.z * g1 + f2.z * g2 + f3.z * g3;
            acc.w += f0.w * g0 + f1.w * g1 + f2.w * g2 + f3.w * g3;

            if (!more) { r = rn; break; }
            f0 = f0n; f1 = f1n; f2 = f2n; f3 = f3n;
            r = rn;
        }
    }

    // ---- tail rows (0..3) ----
    for (; r < end; ++r) {
        const float4 f =
            reinterpret_cast<const float4*>(feats)[(size_t)r * (D_DIM / 4) + lane];
        float p = f.x * wv.x + f.y * wv.y + f.z * wv.z + f.w * wv.w;
#pragma unroll
        for (int o = 16; o > 0; o >>= 1) p += __shfl_xor_sync(0xffffffffu, p, o);
        const float g = SIGMOID(p + bias);
        acc.x += f.x * g;
        acc.y += f.y * g;
        acc.z += f.z * g;
        acc.w += f.w * g;
    }

    // ---- exclusive owner: single plain store (zeros for empty segments) ----
    *reinterpret_cast<float4*>(out + (size_t)s * D_DIM + lane * 4) = acc;
}

extern "C" void kernel_launch(void* const* d_in, const int* in_sizes, int n_in,
                              void* d_out, int out_size)
{
    const float* feats = (const float*)d_in[0];
    const int*   seg   = (const int*)d_in[1];
    const float* w     = (const float*)d_in[2];
    const float* b     = (const float*)d_in[3];
    float*       out   = (float*)d_out;

    const int N = in_sizes[1];            // rows
    const int B = out_size / D_DIM;       // segments (65536)

    const int groups = (N + 3) / 4;
    offs_kernel<<<(groups + 255) / 256, 256>>>(seg, N, B);

    const int blocks = (B + WARPS - 1) / WARPS;

    cudaLaunchConfig_t cfg = {};
    cfg.gridDim  = dim3(blocks, 1, 1);
    cfg.blockDim = dim3(THREADS, 1, 1);
    cfg.dynamicSmemBytes = 0;
    cfg.stream = 0;
    cudaLaunchAttribute attrs[1];
    attrs[0].id = cudaLaunchAttributeProgrammaticStreamSerialization;
    attrs[0].val.programmaticStreamSerializationAllowed = 1;
    cfg.attrs = attrs;
    cfg.numAttrs = 1;

    cudaError_t e = cudaLaunchKernelEx(&cfg, was_kernel, feats, w, b, out, B, N);
    if (e != cudaSuccess) {
        // fallback: plain launch (serialized)
        was_kernel<<<blocks, THREADS>>>(feats, w, b, out, B, N);
    }
}

// round 14
// speedup vs baseline: 1.2614x; 1.2614x over previous
#include <cuda_runtime.h>
#include <cuda_bf16.h>

// WeightAndSum: out[s, :] = sum_{r in segment s} feats[r,:] * sigmoid(dot(feats[r,:], w) + b)
// N = 2,000,000 rows, D = 128, B = 65536 segments, segment_ids sorted ascending.
//
// Two-kernel plan, zero atomics, zero memset (R12 config — proven best —
// plus streaming output stores):
//  1) offs_kernel (vectorized int4, shuffle for prev): g_offs[b] = first row
//     of segment b, g_offs[B] = N.
//  2) was_kernel: warp per segment, exclusive ownership, branchless
//     double-buffered 4-row pipeline, __fdividef sigmoid, PDL launch,
//     THREADS=128. Output written once per lane per segment with st.global.cs
//     (evict-first) so the 33.5MB output stream does not pollute L2 capacity
//     needed by the feats read stream. R13's L2 prefetch removed: it inflated
//     DRAM traffic ~30% (prefetched lines evicted before demand use).

#define D_DIM 128
#define THREADS 128
#define WARPS (THREADS / 32)
#define MAX_B 65536

#define SIGMOID(t) __fdividef(1.0f, 1.0f + __expf(-(t)))

__device__ int g_offs[MAX_B + 1];

__device__ __forceinline__ void stcs4(float* p, float4 v) {
    asm volatile("st.global.cs.v4.f32 [%0], {%1, %2, %3, %4};"
                 :: "l"(p), "f"(v.x), "f"(v.y), "f"(v.z), "f"(v.w) : "memory");
}

__global__ __launch_bounds__(256) void offs_kernel(
    const int* __restrict__ seg, int N, int B)
{
    const int i    = blockIdx.x * blockDim.x + threadIdx.x;
    const int base = i * 4;
    const int lane = threadIdx.x & 31;

    int ids[4] = {0, 0, 0, 0};
    const bool active = (base < N);
    if (active) {
        if (base + 4 <= N) {
            const int4 v = *reinterpret_cast<const int4*>(seg + base);
            ids[0] = v.x; ids[1] = v.y; ids[2] = v.z; ids[3] = v.w;
        } else {
#pragma unroll
            for (int k = 0; k < 4; ++k)
                ids[k] = (base + k < N) ? __ldg(seg + base + k) : 0;
        }
    }

    // prev = seg[base-1]: lane l-1 holds it as ids[3]; warp-edge lanes load it
    const int up = __shfl_up_sync(0xffffffffu, ids[3], 1);
    int prev;
    if (lane == 0)
        prev = (base == 0) ? -1 : __ldg(seg + base - 1);
    else
        prev = up;

    if (!active) return;

    int p = prev;
#pragma unroll
    for (int k = 0; k < 4; ++k) {
        if (base + k >= N) break;
        const int s = ids[k];
        for (int bb = p + 1; bb <= s; ++bb) g_offs[bb] = base + k;
        p = s;
        if (base + k == N - 1)
            for (int bb = s + 1; bb <= B; ++bb) g_offs[bb] = N;
    }
}

__global__ __launch_bounds__(THREADS) void was_kernel(
    const float* __restrict__ feats,
    const float* __restrict__ w,
    const float* __restrict__ b,
    float*       __restrict__ out,
    int B)
{
    const int wid  = threadIdx.x >> 5;
    const int lane = threadIdx.x & 31;
    const int s    = blockIdx.x * WARPS + wid;

    // setup that does NOT depend on g_offs — overlaps offs_kernel via PDL
    const float4 wv  = reinterpret_cast<const float4*>(w)[lane];
    const float bias = __ldg(b);

#if __CUDA_ARCH__ >= 900
    cudaGridDependencySynchronize();
#endif

    if (s >= B) return;

    const int start = __ldg(&g_offs[s]);
    const int end   = __ldg(&g_offs[s + 1]);

    float4 acc = make_float4(0.f, 0.f, 0.f, 0.f);

    int r = start;
    const int stop = start + ((end - start) & ~3);  // full 4-row groups

    if (r < stop) {
        // ---- prologue: load group 0 ----
        const float4* base =
            reinterpret_cast<const float4*>(feats) + (size_t)r * (D_DIM / 4) + lane;
        float4 f0 = __ldcs(base);
        float4 f1 = __ldcs(base + (D_DIM / 4));
        float4 f2 = __ldcs(base + 2 * (D_DIM / 4));
        float4 f3 = __ldcs(base + 3 * (D_DIM / 4));

        for (;;) {
            const int rn    = r + 4;
            const bool more = (rn < stop);

            // ---- prefetch next group before current chain ----
            float4 f0n, f1n, f2n, f3n;
            if (more) {
                const float4* bn =
                    reinterpret_cast<const float4*>(feats) + (size_t)rn * (D_DIM / 4) + lane;
                f0n = __ldcs(bn);
                f1n = __ldcs(bn + (D_DIM / 4));
                f2n = __ldcs(bn + 2 * (D_DIM / 4));
                f3n = __ldcs(bn + 3 * (D_DIM / 4));
            }

            // ---- 4 per-lane partial dots, 4 parallel butterflies ----
            float p0 = f0.x * wv.x + f0.y * wv.y + f0.z * wv.z + f0.w * wv.w;
            float p1 = f1.x * wv.x + f1.y * wv.y + f1.z * wv.z + f1.w * wv.w;
            float p2 = f2.x * wv.x + f2.y * wv.y + f2.z * wv.z + f2.w * wv.w;
            float p3 = f3.x * wv.x + f3.y * wv.y + f3.z * wv.z + f3.w * wv.w;

#pragma unroll
            for (int o = 16; o > 0; o >>= 1) {
                p0 += __shfl_xor_sync(0xffffffffu, p0, o);
                p1 += __shfl_xor_sync(0xffffffffu, p1, o);
                p2 += __shfl_xor_sync(0xffffffffu, p2, o);
                p3 += __shfl_xor_sync(0xffffffffu, p3, o);
            }

            const float g0 = SIGMOID(p0 + bias);
            const float g1 = SIGMOID(p1 + bias);
            const float g2 = SIGMOID(p2 + bias);
            const float g3 = SIGMOID(p3 + bias);

            // ---- branchless accumulate (single owner: no flush logic) ----
            acc.x += f0.x * g0 + f1.x * g1 + f2.x * g2 + f3.x * g3;
            acc.y += f0.y * g0 + f1.y * g1 + f2.y * g2 + f3.y * g3;
            acc.z += f0.z * g0 + f1.z * g1 + f2.z * g2 + f3.z * g3;
            acc.w += f0.w * g0 + f1.w * g1 + f2.w * g2 + f3.w * g3;

            if (!more) { r = rn; break; }
            f0 = f0n; f1 = f1n; f2 = f2n; f3 = f3n;
            r = rn;
        }
    }

    // ---- tail rows (0..3) ----
    for (; r < end; ++r) {
        const float4 f =
            reinterpret_cast<const float4*>(feats)[(size_t)r * (D_DIM / 4) + lane];
        float p = f.x * wv.x + f.y * wv.y + f.z * wv.z + f.w * wv.w;
#pragma unroll
        for (int o = 16; o > 0; o >>= 1) p += __shfl_xor_sync(0xffffffffu, p, o);
        const float g = SIGMOID(p + bias);
        acc.x += f.x * g;
        acc.y += f.y * g;
        acc.z += f.z * g;
        acc.w += f.w * g;
    }

    // ---- exclusive owner: single streaming store (zeros for empties) ----
    stcs4(out + (size_t)s * D_DIM + lane * 4, acc);
}

extern "C" void kernel_launch(void* const* d_in, const int* in_sizes, int n_in,
                              void* d_out, int out_size)
{
    const float* feats = (const float*)d_in[0];
    const int*   seg   = (const int*)d_in[1];
    const float* w     = (const float*)d_in[2];
    const float* b     = (const float*)d_in[3];
    float*       out   = (float*)d_out;

    const int N = in_sizes[1];            // rows
    const int B = out_size / D_DIM;       // segments (65536)

    const int groups = (N + 3) / 4;
    offs_kernel<<<(groups + 255) / 256, 256>>>(seg, N, B);

    const int blocks = (B + WARPS - 1) / WARPS;

    cudaLaunchConfig_t cfg = {};
    cfg.gridDim  = dim3(blocks, 1, 1);
    cfg.blockDim = dim3(THREADS, 1, 1);
    cfg.dynamicSmemBytes = 0;
    cfg.stream = 0;
    cudaLaunchAttribute attrs[1];
    attrs[0].id = cudaLaunchAttributeProgrammaticStreamSerialization;
    attrs[0].val.programmaticStreamSerializationAllowed = 1;
    cfg.attrs = attrs;
    cfg.numAttrs = 1;

    cudaError_t e = cudaLaunchKernelEx(&cfg, was_kernel, feats, w, b, out, B);
    if (e != cudaSuccess) {
        // fallback: plain launch (serialized)
        was_kernel<<<blocks, THREADS>>>(feats, w, b, out, B);
    }
}

// round 17
// speedup vs baseline: 1.2778x; 1.0130x over previous
#include <cuda_runtime.h>
#include <cuda_bf16.h>

// WeightAndSum: out[s, :] = sum_{r in segment s} feats[r,:] * sigmoid(dot(feats[r,:], w) + b)
// N = 2,000,000 rows, D = 128, B = 65536 segments, segment_ids sorted ascending.
//
// Two-kernel plan, zero atomics, zero memset (R14 config + tanh.approx gate):
//  1) offs_kernel (vectorized int4, shuffle for prev): g_offs[b] = first row
//     of segment b, g_offs[B] = N.
//  2) was_kernel: warp per segment, exclusive ownership, branchless
//     double-buffered 4-row pipeline, 4 parallel shuffle butterflies.
//     Gate: sigmoid(x) = 0.5*tanh(x/2)+0.5 via single-instruction
//     tanh.approx.f32 (MUFU) — halves the post-reduction serial chain vs
//     EX2+FADD+RCP+FMUL. st.global.cs output; PDL launch; THREADS=128.
//     (redux.sync.add.f32 is NOT available on sm_103 — R15 build failure.)

#define D_DIM 128
#define THREADS 128
#define WARPS (THREADS / 32)
#define MAX_B 65536

__device__ __forceinline__ float tanh_ap(float x) {
    float y;
    asm("tanh.approx.f32 %0, %1;" : "=f"(y) : "f"(x));
    return y;
}
// sigmoid(t) = 0.5*tanh(0.5*t) + 0.5
#define SIGMOID(t) __fmaf_rn(0.5f, tanh_ap(0.5f * (t)), 0.5f)

__device__ int g_offs[MAX_B + 1];

__device__ __forceinline__ void stcs4(float* p, float4 v) {
    asm volatile("st.global.cs.v4.f32 [%0], {%1, %2, %3, %4};"
                 :: "l"(p), "f"(v.x), "f"(v.y), "f"(v.z), "f"(v.w) : "memory");
}

__global__ __launch_bounds__(256) void offs_kernel(
    const int* __restrict__ seg, int N, int B)
{
    const int i    = blockIdx.x * blockDim.x + threadIdx.x;
    const int base = i * 4;
    const int lane = threadIdx.x & 31;

    int ids[4] = {0, 0, 0, 0};
    const bool active = (base < N);
    if (active) {
        if (base + 4 <= N) {
            const int4 v = __ldcs(reinterpret_cast<const int4*>(seg + base));
            ids[0] = v.x; ids[1] = v.y; ids[2] = v.z; ids[3] = v.w;
        } else {
#pragma unroll
            for (int k = 0; k < 4; ++k)
                ids[k] = (base + k < N) ? __ldg(seg + base + k) : 0;
        }
    }

    // prev = seg[base-1]: lane l-1 holds it as ids[3]; warp-edge lanes load it
    const int up = __shfl_up_sync(0xffffffffu, ids[3], 1);
    int prev;
    if (lane == 0)
        prev = (base == 0) ? -1 : __ldg(seg + base - 1);
    else
        prev = up;

    if (!active) return;

    int p = prev;
#pragma unroll
    for (int k = 0; k < 4; ++k) {
        if (base + k >= N) break;
        const int s = ids[k];
        for (int bb = p + 1; bb <= s; ++bb) g_offs[bb] = base + k;
        p = s;
        if (base + k == N - 1)
            for (int bb = s + 1; bb <= B; ++bb) g_offs[bb] = N;
    }
}

__global__ __launch_bounds__(THREADS) void was_kernel(
    const float* __restrict__ feats,
    const float* __restrict__ w,
    const float* __restrict__ b,
    float*       __restrict__ out,
    int B)
{
    const int wid  = threadIdx.x >> 5;
    const int lane = threadIdx.x & 31;
    const int s    = blockIdx.x * WARPS + wid;

    // setup that does NOT depend on g_offs — overlaps offs_kernel via PDL
    const float4 wv  = reinterpret_cast<const float4*>(w)[lane];
    const float bias = __ldg(b);

#if __CUDA_ARCH__ >= 900
    cudaGridDependencySynchronize();
#endif

    if (s >= B) return;

    const int start = __ldg(&g_offs[s]);
    const int end   = __ldg(&g_offs[s + 1]);

    float4 acc = make_float4(0.f, 0.f, 0.f, 0.f);

    int r = start;
    const int stop = start + ((end - start) & ~3);  // full 4-row groups

    if (r < stop) {
        // ---- prologue: load group 0 ----
        const float4* base =
            reinterpret_cast<const float4*>(feats) + (size_t)r * (D_DIM / 4) + lane;
        float4 f0 = __ldcs(base);
        float4 f1 = __ldcs(base + (D_DIM / 4));
        float4 f2 = __ldcs(base + 2 * (D_DIM / 4));
        float4 f3 = __ldcs(base + 3 * (D_DIM / 4));

        for (;;) {
            const int rn    = r + 4;
            const bool more = (rn < stop);

            // ---- prefetch next group before current chain ----
            float4 f0n, f1n, f2n, f3n;
            if (more) {
                const float4* bn =
                    reinterpret_cast<const float4*>(feats) + (size_t)rn * (D_DIM / 4) + lane;
                f0n = __ldcs(bn);
                f1n = __ldcs(bn + (D_DIM / 4));
                f2n = __ldcs(bn + 2 * (D_DIM / 4));
                f3n = __ldcs(bn + 3 * (D_DIM / 4));
            }

            // ---- 4 per-lane partial dots, 4 parallel butterflies ----
            float p0 = f0.x * wv.x + f0.y * wv.y + f0.z * wv.z + f0.w * wv.w;
            float p1 = f1.x * wv.x + f1.y * wv.y + f1.z * wv.z + f1.w * wv.w;
            float p2 = f2.x * wv.x + f2.y * wv.y + f2.z * wv.z + f2.w * wv.w;
            float p3 = f3.x * wv.x + f3.y * wv.y + f3.z * wv.z + f3.w * wv.w;

#pragma unroll
            for (int o = 16; o > 0; o >>= 1) {
                p0 += __shfl_xor_sync(0xffffffffu, p0, o);
                p1 += __shfl_xor_sync(0xffffffffu, p1, o);
                p2 += __shfl_xor_sync(0xffffffffu, p2, o);
                p3 += __shfl_xor_sync(0xffffffffu, p3, o);
            }

            const float g0 = SIGMOID(p0 + bias);
            const float g1 = SIGMOID(p1 + bias);
            const float g2 = SIGMOID(p2 + bias);
            const float g3 = SIGMOID(p3 + bias);

            // ---- branchless accumulate (single owner: no flush logic) ----
            acc.x += f0.x * g0 + f1.x * g1 + f2.x * g2 + f3.x * g3;
            acc.y += f0.y * g0 + f1.y * g1 + f2.y * g2 + f3.y * g3;
            acc.z += f0.z * g0 + f1.z * g1 + f2.z * g2 + f3.z * g3;
            acc.w += f0.w * g0 + f1.w * g1 + f2.w * g2 + f3.w * g3;

            if (!more) { r = rn; break; }
            f0 = f0n; f1 = f1n; f2 = f2n; f3 = f3n;
            r = rn;
        }
    }

    // ---- tail rows (0..3) ----
    for (; r < end; ++r) {
        const float4 f =
            reinterpret_cast<const float4*>(feats)[(size_t)r * (D_DIM / 4) + lane];
        float p = f.x * wv.x + f.y * wv.y + f.z * wv.z + f.w * wv.w;
#pragma unroll
        for (int o = 16; o > 0; o >>= 1) p += __shfl_xor_sync(0xffffffffu, p, o);
        const float g = SIGMOID(p + bias);
        acc.x += f.x * g;
        acc.y += f.y * g;
        acc.z += f.z * g;
        acc.w += f.w * g;
    }

    // ---- exclusive owner: single streaming store (zeros for empties) ----
    stcs4(out + (size_t)s * D_DIM + lane * 4, acc);
}

extern "C" void kernel_launch(void* const* d_in, const int* in_sizes, int n_in,
                              void* d_out, int out_size)
{
    const float* feats = (const float*)d_in[0];
    const int*   seg   = (const int*)d_in[1];
    const float* w     = (const float*)d_in[2];
    const float* b     = (const float*)d_in[3];
    float*       out   = (float*)d_out;

    const int N = in_sizes[1];            // rows
    const int B = out_size / D_DIM;       // segments (65536)

    const int groups = (N + 3) / 4;
    offs_kernel<<<(groups + 255) / 256, 256>>>(seg, N, B);

    const int blocks = (B + WARPS - 1) / WARPS;

    cudaLaunchConfig_t cfg = {};
    cfg.gridDim  = dim3(blocks, 1, 1);
    cfg.blockDim = dim3(THREADS, 1, 1);
    cfg.dynamicSmemBytes = 0;
    cfg.stream = 0;
    cudaLaunchAttribute attrs[1];
    attrs[0].id = cudaLaunchAttributeProgrammaticStreamSerialization;
    attrs[0].val.programmaticStreamSerializationAllowed = 1;
    cfg.attrs = attrs;
    cfg.numAttrs = 1;

    cudaError_t e = cudaLaunchKernelEx(&cfg, was_kernel, feats, w, b, out, B);
    if (e != cudaSuccess) {
        // fallback: plain launch (serialized)
        was_kernel<<<blocks, THREADS>>>(feats, w, b, out, B);
    }
}